// round 10
// baseline (speedup 1.0000x reference)
#include <cuda_runtime.h>
#include <cuda_fp16.h>
#include <cstdint>

#define D_DIM 1024
#define T_DIM 512
#define BM    64
#define BN    256                // per-CTA N half (cluster of 2 covers T=512)
#define KC    32                 // k-floats per stage (fp16 rows = 64 B)
#define NSTAGES 32
#define NTHREADS 512
#define NBUF  4

// ---- smem layout (bytes) ----
#define SO_BH   0                // 256 floats (own half bias)
#define SO_WS   1024             // 8 x 64 floats per 32-col-block row sums
#define SO_BASE 3072             // 64 floats
#define SO_RECV 3328             // 64 floats (left-half totals, rank1 only)
#define SO_A    3584             // 4 x 4096   (64 rows x 64B fp16)
#define SO_B    19968            // 4 x 16384  (256 rows x 64B fp16)
#define A_BUF   4096
#define B_BUF   16384
#define SMEM_BYTES 85504

__device__ __forceinline__ unsigned smem_u32(const void* p) {
    unsigned a;
    asm("{ .reg .u64 t; cvta.to.shared.u64 t, %1; cvt.u32.u64 %0, t; }" : "=r"(a) : "l"(p));
    return a;
}

__device__ __forceinline__ unsigned cvt2(float lo, float hi) {
    unsigned r;
    asm("cvt.rn.f16x2.f32 %0, %1, %2;" : "=r"(r) : "f"(hi), "f"(lo));
    return r;
}

__device__ __forceinline__ unsigned lds32(unsigned a) {
    unsigned v;
    asm volatile("ld.shared.b32 %0, [%1];" : "=r"(v) : "r"(a));
    return v;
}

__device__ __forceinline__ void mma_f16(float* c, const unsigned* a, const unsigned* b) {
    asm volatile(
        "mma.sync.aligned.m16n8k16.row.col.f32.f16.f16.f32 "
        "{%0,%1,%2,%3},{%4,%5,%6,%7},{%8,%9},{%0,%1,%2,%3};"
        : "+f"(c[0]), "+f"(c[1]), "+f"(c[2]), "+f"(c[3])
        : "r"(a[0]), "r"(a[1]), "r"(a[2]), "r"(a[3]), "r"(b[0]), "r"(b[1]));
}

__global__ __launch_bounds__(NTHREADS, 2) __cluster_dims__(2, 1, 1)
void surv_k10(const float* __restrict__ x,
              const float* __restrict__ Wh,
              const float* __restrict__ bh,
              const float* __restrict__ Wb,
              const float* __restrict__ bb,
              float* __restrict__ out) {
    extern __shared__ char smem[];
    const unsigned sb = smem_u32(smem);
    float* bhs   = (float*)(smem + SO_BH);
    float* ws    = (float*)(smem + SO_WS);
    float* basef = (float*)(smem + SO_BASE);
    float* recvf = (float*)(smem + SO_RECV);

    const int tid  = threadIdx.x;
    const int warp = tid >> 5;
    const int lane = tid & 31;
    const int g    = lane >> 2;
    const int tig  = lane & 3;
    const int wm   = warp & 1;      // M half (32 rows)
    const int wn   = warp >> 1;     // N block (32 cols each, 0..7)

    const int rank    = blockIdx.x & 1;     // cluster ctarank (T half)
    const int mtile   = blockIdx.x >> 1;
    const int colbase = rank * BN;

    if (tid < BN) bhs[tid] = bh[colbase + tid];

    // ---- staging addressing ----
    const int srow = tid >> 3;      // 0..63
    const int sj   = tid & 7;       // 4-float chunk in the 32-float stage row
    const float* gA = x + (size_t)(mtile * BM + srow) * D_DIM + sj * 4;
    const float* gB = Wh + (size_t)(colbase + srow) * D_DIM + sj * 4;
    unsigned stoA, stoB;
    {
        unsigned o = (unsigned)(srow * 64 + sj * 8);
        o ^= (o >> 3) & 0x30;       // 16B-unit swizzle
        stoA = SO_A + o;
        stoB = SO_B + o;            // +i*4096 per 64-row group preserves swizzle
    }

    auto load_stage = [&](int s, int buf) {
        const int k0 = s * KC;
        {
            float4 v = *(const float4*)(gA + k0);
            uint2 h;
            h.x = cvt2(v.x, v.y);
            h.y = cvt2(v.z, v.w);
            *(uint2*)(smem + stoA + buf * A_BUF) = h;
        }
        char* bp = smem + stoB + buf * B_BUF;
#pragma unroll
        for (int i = 0; i < 4; i++) {
            float4 v = *(const float4*)(gB + (size_t)(i * 64) * D_DIM + k0);
            uint2 h;
            h.x = cvt2(v.x, v.y);
            h.y = cvt2(v.z, v.w);
            *(uint2*)(bp + i * 4096) = h;
        }
    };

    float acc[2][4][4];
#pragma unroll
    for (int mt = 0; mt < 2; mt++)
#pragma unroll
        for (int nt = 0; nt < 4; nt++)
#pragma unroll
            for (int i = 0; i < 4; i++) acc[mt][nt][i] = 0.f;

    // ---- fragment addressing ----
    const unsigned key = (unsigned)((g & 6) << 3);
    const unsigned C0 = key;
    const unsigned C1 = 16u ^ key;
    const unsigned C2 = 32u ^ key;
    const unsigned C3 = 48u ^ key;
    const unsigned paw = sb + SO_A + (unsigned)((wm * 32 + g) * 64 + tig * 4);
    const unsigned pbw = sb + SO_B + (unsigned)((wn * 32 + g) * 64 + tig * 4);

    auto compute_stage = [&](int buf) {
        const unsigned ab  = paw + buf * A_BUF;
        const unsigned bbs = pbw + buf * B_BUF;
#pragma unroll
        for (int kk = 0; kk < 2; kk++) {
            const unsigned cu0 = kk ? C2 : C0;
            const unsigned cu1 = kk ? C3 : C1;
            unsigned afr[2][4];
#pragma unroll
            for (int mt = 0; mt < 2; mt++) {
                const unsigned a0 = ab + mt * 1024;          // 16 rows * 64B
                afr[mt][0] = lds32(a0 + cu0);
                afr[mt][1] = lds32(a0 + 512 + cu0);          // +8 rows
                afr[mt][2] = lds32(a0 + cu1);
                afr[mt][3] = lds32(a0 + 512 + cu1);
            }
            unsigned bfr[4][2];
#pragma unroll
            for (int nt = 0; nt < 4; nt++) {
                const unsigned b0 = bbs + nt * 512;          // 8 rows * 64B
                bfr[nt][0] = lds32(b0 + cu0);
                bfr[nt][1] = lds32(b0 + cu1);
            }
#pragma unroll
            for (int mt = 0; mt < 2; mt++)
#pragma unroll
                for (int nt = 0; nt < 4; nt++)
                    mma_f16(acc[mt][nt], afr[mt], bfr[nt]);
        }
    };

    // ---- pipeline: NBUF=4, one barrier per 2 stages ----
    load_stage(0, 0);
    load_stage(1, 1);
    __syncthreads();

#pragma unroll 2
    for (int p = 0; p < NSTAGES / 2; p++) {
        const int s0 = 2 * p;
        if (s0 + 2 < NSTAGES) load_stage(s0 + 2, (s0 + 2) & 3);
        compute_stage(s0 & 3);
        if (s0 + 3 < NSTAGES) load_stage(s0 + 3, (s0 + 3) & 3);
        compute_stage((s0 + 1) & 3);
        __syncthreads();
    }

    // ---- epilogue ----
    const unsigned fullm = 0xffffffffu;
    // 1) relu + bias + in-register inclusive scan within each 32-col warp block
#pragma unroll
    for (int mt = 0; mt < 2; mt++) {
#pragma unroll
        for (int h = 0; h < 2; h++) {
            float run = 0.f;
            const int rowlocal = wm * 32 + mt * 16 + g + h * 8;
#pragma unroll
            for (int nt = 0; nt < 4; nt++) {
                const int c = wn * 32 + nt * 8 + tig * 2;
                float v0 = fmaxf(acc[mt][nt][2 * h + 0] + bhs[c], 0.f);
                float v1 = fmaxf(acc[mt][nt][2 * h + 1] + bhs[c + 1], 0.f);
                float pair = v0 + v1;
                float incl = pair;
                float t = __shfl_up_sync(fullm, incl, 1, 4);
                if (tig >= 1) incl += t;
                t = __shfl_up_sync(fullm, incl, 2, 4);
                if (tig >= 2) incl += t;
                float excl = incl - pair;
                acc[mt][nt][2 * h + 0] = run + excl + v0;
                acc[mt][nt][2 * h + 1] = run + excl + pair;
                run += __shfl_sync(fullm, incl, 3, 4);
            }
            if (tig == 0) ws[wn * 64 + rowlocal] = run;
        }
    }

    // 2) base term: base[r] = bb + x[r,:].Wb (8 threads/row, fp32)
    {
        const int r = tid >> 3;
        const int part = tid & 7;
        const float* xr = x + (size_t)(mtile * BM + r) * D_DIM + part * 128;
        const float* wr = Wb + part * 128;
        float pdot = 0.f;
#pragma unroll
        for (int i = 0; i < 32; i++) {
            float4 a = ((const float4*)xr)[i];
            float4 w = ((const float4*)wr)[i];
            pdot += a.x * w.x + a.y * w.y + a.z * w.z + a.w * w.w;
        }
        pdot += __shfl_xor_sync(fullm, pdot, 4, 8);
        pdot += __shfl_xor_sync(fullm, pdot, 2, 8);
        pdot += __shfl_xor_sync(fullm, pdot, 1, 8);
        if (part == 0) basef[r] = pdot + __ldg(bb);
    }
    __syncthreads();

    // 3) rank 0 sends its per-row hazard totals to rank 1's SO_RECV
    if (rank == 0 && tid < BM) {
        float tot = 0.f;
#pragma unroll
        for (int j = 0; j < 8; j++) tot += ws[j * 64 + tid];
        unsigned remote;
        asm("mapa.shared::cluster.u32 %0, %1, %2;"
            : "=r"(remote) : "r"(sb + SO_RECV + tid * 4), "r"(1));
        asm volatile("st.shared::cluster.f32 [%0], %1;" :: "r"(remote), "f"(tot));
    }
    asm volatile("barrier.cluster.arrive.aligned;" ::: "memory");
    asm volatile("barrier.cluster.wait.aligned;" ::: "memory");

    // 4) add offsets and store
#pragma unroll
    for (int mt = 0; mt < 2; mt++) {
#pragma unroll
        for (int h = 0; h < 2; h++) {
            const int rowlocal = wm * 32 + mt * 16 + g + h * 8;
            float off = basef[rowlocal];
            if (rank) off += recvf[rowlocal];
            for (int j = 0; j < wn; j++) off += ws[j * 64 + rowlocal];
            float* orow = out + (size_t)(mtile * BM + rowlocal) * T_DIM + colbase;
#pragma unroll
            for (int nt = 0; nt < 4; nt++) {
                const int c = wn * 32 + nt * 8 + tig * 2;
                float2 v;
                v.x = off + acc[mt][nt][2 * h + 0];
                v.y = off + acc[mt][nt][2 * h + 1];
                *(float2*)(orow + c) = v;
            }
        }
    }
}

extern "C" void kernel_launch(void* const* d_in, const int* in_sizes, int n_in,
                              void* d_out, int out_size) {
    const float* x  = (const float*)d_in[0];
    const float* Wh = (const float*)d_in[1];
    const float* bh = (const float*)d_in[2];
    const float* Wb = (const float*)d_in[3];
    const float* bb = (const float*)d_in[4];
    float* out = (float*)d_out;

    cudaFuncSetAttribute(surv_k10, cudaFuncAttributeMaxDynamicSharedMemorySize, SMEM_BYTES);
    surv_k10<<<(16384 / BM) * 2, NTHREADS, SMEM_BYTES>>>(x, Wh, bh, Wb, bb, out);
}

// round 12
// speedup vs baseline: 1.5653x; 1.5653x over previous
#include <cuda_runtime.h>
#include <cuda_fp16.h>
#include <cstdint>

#define D_DIM 1024
#define T_DIM 512
#define BM    64
#define KC    32                 // k-floats per stage (fp16 rows = 64 B)
#define NSTAGES 32
#define NTHREADS 512
#define NBUF  4

// ---- smem layout (bytes) ----
#define SO_BH   0                // 512 floats bias
#define SO_WS   2048             // 8 x 64 floats per-block row sums
#define SO_BASE 4096             // 64 floats
#define SO_A    4352             // 4 x 4096   (64 rows x 64B fp16)
#define SO_B    20736            // 4 x 32768  (512 rows x 64B fp16)
#define A_BUF   4096
#define B_BUF   32768
#define SMEM_BYTES 151808

// Pre-converted, pre-swizzled Wh: 32 stage blocks of 32KB each (fp16)
__device__ __half whB_dev[NSTAGES * 16384];

__device__ __forceinline__ unsigned smem_u32(const void* p) {
    unsigned a;
    asm("{ .reg .u64 t; cvta.to.shared.u64 t, %1; cvt.u32.u64 %0, t; }" : "=r"(a) : "l"(p));
    return a;
}

__device__ __forceinline__ unsigned cvt2(float lo, float hi) {
    unsigned r;
    asm("cvt.rn.f16x2.f32 %0, %1, %2;" : "=r"(r) : "f"(hi), "f"(lo));
    return r;
}

__device__ __forceinline__ unsigned lds32(unsigned a) {
    unsigned v;
    asm volatile("ld.shared.b32 %0, [%1];" : "=r"(v) : "r"(a));
    return v;
}

__device__ __forceinline__ void cp16(unsigned dst, const void* src) {
    asm volatile("cp.async.cg.shared.global [%0], [%1], 16;" :: "r"(dst), "l"(src) : "memory");
}
#define CP_COMMIT() asm volatile("cp.async.commit_group;" ::: "memory")
#define CP_WAIT0()  asm volatile("cp.async.wait_group 0;" ::: "memory")

__device__ __forceinline__ void mma_f16(float* c, const unsigned* a, const unsigned* b) {
    asm volatile(
        "mma.sync.aligned.m16n8k16.row.col.f32.f16.f16.f32 "
        "{%0,%1,%2,%3},{%4,%5,%6,%7},{%8,%9},{%0,%1,%2,%3};"
        : "+f"(c[0]), "+f"(c[1]), "+f"(c[2]), "+f"(c[3])
        : "r"(a[0]), "r"(a[1]), "r"(a[2]), "r"(a[3]), "r"(b[0]), "r"(b[1]));
}

// ---- prologue: convert + pre-swizzle Wh into stage-major fp16 blocks ----
__global__ void cvt_wh(const float* __restrict__ Wh) {
    const int idx = blockIdx.x * 256 + threadIdx.x;  // 0 .. 524287
    const int r = idx >> 10;          // row 0..511
    const int k = idx & 1023;         // column 0..1023
    const int s = k >> 5;             // stage
    const int w = k & 31;             // within-stage col
    const int c = w >> 2;             // 8B chunk (4 halfs)
    const int e = w & 3;
    unsigned off = (unsigned)(r * 64 + c * 8);
    off ^= (off >> 3) & 0x30;         // same swizzle the mainloop fragments expect
    whB_dev[s * 16384 + (off >> 1) + e] = __float2half_rn(Wh[idx]);
}

__global__ __launch_bounds__(NTHREADS, 1)
void surv_k11(const float* __restrict__ x,
              const float* __restrict__ bh,
              const float* __restrict__ Wb,
              const float* __restrict__ bb,
              float* __restrict__ out) {
    extern __shared__ char smem[];
    const unsigned sb = smem_u32(smem);
    float* bhs   = (float*)(smem + SO_BH);
    float* ws    = (float*)(smem + SO_WS);
    float* basef = (float*)(smem + SO_BASE);

    const int tid  = threadIdx.x;
    const int warp = tid >> 5;
    const int lane = tid & 31;
    const int g    = lane >> 2;
    const int tig  = lane & 3;
    const int wm   = warp & 1;      // M half (32 rows)
    const int wn   = warp >> 1;     // N block (64 cols)

    bhs[tid] = bh[tid];

    // ---- A staging addressing (fp32 -> fp16, 8B per thread per stage) ----
    const int srow = tid >> 3;      // 0..63
    const int sj   = tid & 7;       // 8B chunk in a 64B fp16 row
    const float* gA = x + (size_t)(blockIdx.x * BM + srow) * D_DIM + sj * 4;
    unsigned stoA;
    {
        unsigned o = (unsigned)(srow * 64 + sj * 8);
        o ^= (o >> 3) & 0x30;
        stoA = SO_A + o;
    }
    // ---- B staging: linear copy of pre-swizzled image ----
    const char* gWB = (const char*)whB_dev + tid * 16;
    const unsigned stoB = sb + SO_B + (unsigned)tid * 16;

    auto cpB = [&](int s, int buf) {
        const char* src = gWB + s * 32768;
        const unsigned dst = stoB + buf * B_BUF;
#pragma unroll
        for (int i = 0; i < 4; i++)
            cp16(dst + i * 8192, src + i * 8192);
    };
    auto stA = [&](const float4& v, int buf) {
        uint2 h;
        h.x = cvt2(v.x, v.y);
        h.y = cvt2(v.z, v.w);
        *(uint2*)(smem + stoA + buf * A_BUF) = h;
    };

    float acc[2][8][4];
#pragma unroll
    for (int mt = 0; mt < 2; mt++)
#pragma unroll
        for (int nt = 0; nt < 8; nt++)
#pragma unroll
            for (int i = 0; i < 4; i++) acc[mt][nt][i] = 0.f;

    // ---- fragment addressing (same swizzle family as R9) ----
    const unsigned key = (unsigned)((g & 6) << 3);
    const unsigned C0 = key;
    const unsigned C1 = 16u ^ key;
    const unsigned C2 = 32u ^ key;
    const unsigned C3 = 48u ^ key;
    const unsigned paw = sb + SO_A + (unsigned)((wm * 32 + g) * 64 + tig * 4);
    const unsigned pbw = sb + SO_B + (unsigned)((wn * 64 + g) * 64 + tig * 4);

    auto compute_stage = [&](int buf) {
        const unsigned ab  = paw + buf * A_BUF;
        const unsigned bbs = pbw + buf * B_BUF;
#pragma unroll
        for (int kk = 0; kk < 2; kk++) {
            const unsigned cu0 = kk ? C2 : C0;
            const unsigned cu1 = kk ? C3 : C1;
            unsigned afr[2][4];
#pragma unroll
            for (int mt = 0; mt < 2; mt++) {
                const unsigned a0 = ab + mt * 1024;          // 16 rows * 64B
                afr[mt][0] = lds32(a0 + cu0);
                afr[mt][1] = lds32(a0 + 512 + cu0);          // +8 rows
                afr[mt][2] = lds32(a0 + cu1);
                afr[mt][3] = lds32(a0 + 512 + cu1);
            }
            unsigned bfr[8][2];
#pragma unroll
            for (int nt = 0; nt < 8; nt++) {
                const unsigned b0 = bbs + nt * 512;          // 8 rows * 64B
                bfr[nt][0] = lds32(b0 + cu0);
                bfr[nt][1] = lds32(b0 + cu1);
            }
#pragma unroll
            for (int mt = 0; mt < 2; mt++)
#pragma unroll
                for (int nt = 0; nt < 8; nt++)
                    mma_f16(acc[mt][nt], afr[mt], bfr[nt]);
        }
    };

    // ---- prologue fills stages 0,1 ----
    {
        float4 ra0 = *(const float4*)(gA + 0 * KC);
        float4 ra1 = *(const float4*)(gA + 1 * KC);
        cpB(0, 0);
        cpB(1, 1);
        CP_COMMIT();
        stA(ra0, 0);
        stA(ra1, 1);
        CP_WAIT0();
        __syncthreads();
    }

    // ---- mainloop: 2 stages per barrier, distance-2 prefetch ----
    for (int p = 0; p < NSTAGES / 2; p++) {
        const int s0 = 2 * p;
        float4 ra0, ra1;
        const bool p2 = (s0 + 2 < NSTAGES);
        const bool p3 = (s0 + 3 < NSTAGES);
        if (p2) { ra0 = *(const float4*)(gA + (s0 + 2) * KC); cpB(s0 + 2, (s0 + 2) & 3); }
        if (p3) { ra1 = *(const float4*)(gA + (s0 + 3) * KC); cpB(s0 + 3, (s0 + 3) & 3); }
        CP_COMMIT();
        compute_stage(s0 & 3);
        if (p2) stA(ra0, (s0 + 2) & 3);
        compute_stage((s0 + 1) & 3);
        if (p3) stA(ra1, (s0 + 3) & 3);
        CP_WAIT0();
        __syncthreads();
    }

    // ---- epilogue (identical to R9) ----
    const unsigned fullm = 0xffffffffu;
#pragma unroll
    for (int mt = 0; mt < 2; mt++) {
#pragma unroll
        for (int h = 0; h < 2; h++) {
            float run = 0.f;
            const int rowlocal = wm * 32 + mt * 16 + g + h * 8;
#pragma unroll
            for (int nt = 0; nt < 8; nt++) {
                const int c = wn * 64 + nt * 8 + tig * 2;
                float v0 = fmaxf(acc[mt][nt][2 * h + 0] + bhs[c], 0.f);
                float v1 = fmaxf(acc[mt][nt][2 * h + 1] + bhs[c + 1], 0.f);
                float pair = v0 + v1;
                float incl = pair;
                float t = __shfl_up_sync(fullm, incl, 1, 4);
                if (tig >= 1) incl += t;
                t = __shfl_up_sync(fullm, incl, 2, 4);
                if (tig >= 2) incl += t;
                float excl = incl - pair;
                acc[mt][nt][2 * h + 0] = run + excl + v0;
                acc[mt][nt][2 * h + 1] = run + excl + pair;
                run += __shfl_sync(fullm, incl, 3, 4);
            }
            if (tig == 0) ws[wn * 64 + rowlocal] = run;
        }
    }

    // base term: base[r] = bb + x[r,:].Wb (8 threads/row, fp32)
    {
        const int r = tid >> 3;
        const int part = tid & 7;
        const float* xr = x + (size_t)(blockIdx.x * BM + r) * D_DIM + part * 128;
        const float* wr = Wb + part * 128;
        float pdot = 0.f;
#pragma unroll
        for (int i = 0; i < 32; i++) {
            float4 a = ((const float4*)xr)[i];
            float4 w = ((const float4*)wr)[i];
            pdot += a.x * w.x + a.y * w.y + a.z * w.z + a.w * w.w;
        }
        pdot += __shfl_xor_sync(fullm, pdot, 4, 8);
        pdot += __shfl_xor_sync(fullm, pdot, 2, 8);
        pdot += __shfl_xor_sync(fullm, pdot, 1, 8);
        if (part == 0) basef[r] = pdot + __ldg(bb);
    }
    __syncthreads();

    // add cross-block offsets and store
#pragma unroll
    for (int mt = 0; mt < 2; mt++) {
#pragma unroll
        for (int h = 0; h < 2; h++) {
            const int rowlocal = wm * 32 + mt * 16 + g + h * 8;
            float off = basef[rowlocal];
            for (int j = 0; j < wn; j++) off += ws[j * 64 + rowlocal];
            float* orow = out + (size_t)(blockIdx.x * BM + rowlocal) * T_DIM;
#pragma unroll
            for (int nt = 0; nt < 8; nt++) {
                const int c = wn * 64 + nt * 8 + tig * 2;
                float2 v;
                v.x = off + acc[mt][nt][2 * h + 0];
                v.y = off + acc[mt][nt][2 * h + 1];
                *(float2*)(orow + c) = v;
            }
        }
    }
}

extern "C" void kernel_launch(void* const* d_in, const int* in_sizes, int n_in,
                              void* d_out, int out_size) {
    const float* x  = (const float*)d_in[0];
    const float* Wh = (const float*)d_in[1];
    const float* bh = (const float*)d_in[2];
    const float* Wb = (const float*)d_in[3];
    const float* bb = (const float*)d_in[4];
    float* out = (float*)d_out;

    cvt_wh<<<2048, 256>>>(Wh);

    cudaFuncSetAttribute(surv_k11, cudaFuncAttributeMaxDynamicSharedMemorySize, SMEM_BYTES);
    surv_k11<<<16384 / BM, NTHREADS, SMEM_BYTES>>>(x, bh, Wb, bb, out);
}